// round 17
// baseline (speedup 1.0000x reference)
#include <cuda_runtime.h>
#include <cuda_fp16.h>
#include <cstdint>

#define Bsz 4
#define Cch 256
#define Hh  64
#define Ww  64
#define Oo  256
#define Kt  9
#define Md  (Bsz*Hh*Ww)   // 16384
#define Kd  (Cch*Kt)      // 2304

// ---------------- scratch ----------------
__device__ __half g_nhwcH[(size_t)Bsz*Hh*Ww*Cch];   // fp16 NHWC
__device__ __half g_B[(size_t)Oo*Kd];
__device__ __half g_Boff[(size_t)32*Kd];
__device__ float g_bias2[Oo];

// ---------------- helpers ----------------
__device__ __forceinline__ uint32_t smem_u32(const void* p) {
    uint32_t a;
    asm("{ .reg .u64 t; cvta.to.shared.u64 t, %1; cvt.u32.u64 %0, t; }" : "=r"(a) : "l"(p));
    return a;
}
__device__ __forceinline__ void cpa16(uint32_t s, const void* g) {
    asm volatile("cp.async.cg.shared.global [%0], [%1], 16;" :: "r"(s), "l"(g));
}
__device__ __forceinline__ void cpa16z(uint32_t s, const void* g, int valid) {
    asm volatile("cp.async.cg.shared.global [%0], [%1], 16, %2;"
                 :: "r"(s), "l"(g), "r"(valid ? 16 : 0));
}
#define LDMX4(r, addr) \
    asm volatile("ldmatrix.sync.aligned.m8n8.x4.shared.b16 {%0,%1,%2,%3}, [%4];" \
        : "=r"((r)[0]), "=r"((r)[1]), "=r"((r)[2]), "=r"((r)[3]) : "r"(addr))
#define MMA16816(d, a, b0, b1) \
    asm volatile("mma.sync.aligned.m16n8k16.row.col.f32.f16.f16.f32 " \
        "{%0,%1,%2,%3}, {%4,%5,%6,%7}, {%8,%9}, {%0,%1,%2,%3};" \
        : "+f"((d)[0]), "+f"((d)[1]), "+f"((d)[2]), "+f"((d)[3]) \
        : "r"((a)[0]), "r"((a)[1]), "r"((a)[2]), "r"((a)[3]), "r"(b0), "r"(b1))

// ---------------- 1) transpose to fp16 NHWC + weight prep ----------------
__global__ void k_transpose_prep(const float* __restrict__ in,
                                 const float* __restrict__ w,
                                 const float* __restrict__ w_off,
                                 const float* __restrict__ bias,
                                 const float* __restrict__ gamma,
                                 const float* __restrict__ beta,
                                 const float* __restrict__ mean,
                                 const float* __restrict__ var) {
    const int tx = threadIdx.x, ty = threadIdx.y;
    if (blockIdx.y == 4) {
        int o = blockIdx.z;
        int tid = ty * 32 + tx;
        float inv = gamma[o] * rsqrtf(var[o] + 1e-5f);
        int kd0 = blockIdx.x * (Kd/2);
        for (int i = tid; i < Kd/2; i += 256) {
            int kd = kd0 + i;
            int tap = kd >> 8, c = kd & 255;
            g_B[(size_t)o*Kd + kd] = __float2half_rn(w[((size_t)(o*Cch + c))*9 + tap] * inv);
        }
        if (tid == 0 && blockIdx.x == 0)
            g_bias2[o] = bias[o]*inv + beta[o] - mean[o]*inv;
        return;
    }
    if (blockIdx.y == 5) {
        int j = blockIdx.z;
        if (j >= 32 || blockIdx.x != 0) return;
        int tid = ty * 32 + tx;
        for (int kd = tid; kd < Kd; kd += 256) {
            int tap = kd >> 8, c = kd & 255;
            __half v = __float2half_rn(0.f);
            if (j < 18) v = __float2half_rn(w_off[((size_t)(j*Cch + c))*9 + tap]);
            g_Boff[(size_t)j*Kd + kd] = v;
        }
        return;
    }
    __shared__ float t[64][33];
    const int x0 = blockIdx.x * 32;
    const int c0 = blockIdx.y * 64;
    const int bh = blockIdx.z;
    const int b = bh >> 6, y = bh & 63;
    const float* ib = in + (((size_t)(b*Cch + c0))*Hh + y)*Ww + x0;
    #pragma unroll
    for (int i = 0; i < 8; i++) {
        int r = ty + i*8;
        t[r][tx] = ib[(size_t)r*Hh*Ww + tx];
    }
    __syncthreads();
    __half* ob = g_nhwcH + (((size_t)(b*Hh + y)*Ww + x0) << 8) + c0;
    #pragma unroll
    for (int i = 0; i < 4; i++) {
        int x = ty + i*8;
        __half2 h = __floats2half2_rn(t[2*tx][x], t[2*tx + 1][x]);
        *(__half2*)(ob + ((size_t)x << 8) + 2*tx) = h;
    }
}

// ---------------- 2) merged: offset GEMM prologue + fused sample GEMM ----------------
// phase-2 (main GEMM) region
#define KC 32
#define NCH (Kd/KC)          // 72
#define APL 10240
#define BPL 20480
#define BBASE (2*APL)
#define GEMMSZ (2*APL + 4*BPL)      // 102400
#define SOFF GEMMSZ                 // offsets: 18 x 128 floats
// phase-1 staging region (disjoint, so B prefetch can proceed during phase-1)
#define KC2 32
#define NCH2 (Kd/KC2)        // 72
#define APL2 10240
#define BSM2 2560
#define STG2 (APL2 + BSM2)   // 12800
#define P1BASE (SOFF + 18*128*4)    // 111616
#define SMEMSZ (P1BASE + 4*STG2)    // 162816

__global__ __launch_bounds__(256, 1) void k_fused_all(float* __restrict__ out,
                                                      const float* __restrict__ b_off) {
    extern __shared__ char dsm[];
    const uint32_t sbase = smem_u32(dsm);
    char* dsmp = dsm;
    float* s_off = (float*)(dsm + SOFF);
    const int tid = threadIdx.x, lid = tid & 31, wid = tid >> 5;
    const int m0 = blockIdx.x * 128;
    const int bb = m0 >> 12;
    const int y0 = (m0 >> 6) & 63;
    const int pbase = m0 & 4095;

    // B loader for phase-2 (used for prefetch during phase-1 too)
    auto loadB = [&](int c, int p) {
        uint32_t sb = sbase + BBASE + p * BPL;
        size_t kOff = (size_t)c * KC;
        #pragma unroll
        for (int i = 0; i < 4; i++) {
            int idx = tid + i*256;
            int rr = idx >> 2;
            int j  = idx & 3;
            cpa16(sb + rr*80 + j*16, g_B + (size_t)rr*Kd + kOff + j*8);
        }
        asm volatile("cp.async.commit_group;");
    };

    // prefetch phase-2's first 3 B stages; completes during phase-1
    loadB(0, 0);
    loadB(1, 1);
    loadB(2, 2);

    // ================= phase 1: offset conv for own 128 pixels (N=24 used) =================
    {
        float acc[3][4];
        #pragma unroll
        for (int nt = 0; nt < 3; nt++)
            #pragma unroll
            for (int j = 0; j < 4; j++) acc[nt][j] = 0.f;

        const uint32_t a_off = (uint32_t)(P1BASE + (wid*16 + (lid & 15)) * 80 + (lid >> 4) * 16);
        const uint32_t b_offs = (uint32_t)(P1BASE + APL2 + ((lid & 7) + ((lid >> 4) & 1)*8) * 80
                                           + ((lid >> 3) & 1) * 16);

        auto load = [&](int c, int p) {
            uint32_t sb = sbase + P1BASE + p * STG2;
            int tap = c >> 3;
            int ky = tap / 3 - 1, kx = tap % 3 - 1;
            int c0 = (c & 7) * 32;
            #pragma unroll
            for (int i = 0; i < 2; i++) {
                int idx = tid + i*256;
                int r   = idx >> 2;
                int j   = idx & 3;
                int ry = y0 + (r >> 6) + ky;
                int rx = (r & 63) + kx;
                int valid = ((unsigned)ry < 64u) && ((unsigned)rx < 64u);
                int ryc = min(max(ry, 0), 63), rxc = min(max(rx, 0), 63);
                const __half* src = g_nhwcH + (((size_t)(bb*Hh + ryc)*Ww + rxc) << 8) + c0 + j*8;
                cpa16z(sb + r*80 + j*16, src, valid);
            }
            if (tid < 128) {
                int rr = tid >> 2;
                int j  = tid & 3;
                cpa16(sb + APL2 + rr*80 + j*16, g_Boff + (size_t)rr*Kd + tap*Cch + c0 + j*8);
            }
            asm volatile("cp.async.commit_group;");
        };

        load(0, 0);
        load(1, 1);
        load(2, 2);

        for (int c = 0; c < NCH2; c++) {
            int p = c & 3;
            if (c + 3 < NCH2) {
                load(c + 3, (c + 3) & 3);
                asm volatile("cp.async.wait_group 3;" ::: "memory");
            } else if (c + 2 < NCH2) {
                asm volatile("cp.async.wait_group 2;" ::: "memory");
            } else if (c + 1 < NCH2) {
                asm volatile("cp.async.wait_group 1;" ::: "memory");
            } else {
                asm volatile("cp.async.wait_group 0;" ::: "memory");
            }
            __syncthreads();

            uint32_t stg = (uint32_t)(p * STG2);
            #pragma unroll
            for (int kh = 0; kh < 2; kh++) {
                uint32_t ah[4];
                LDMX4(ah, sbase + a_off + stg + kh*32);
                #pragma unroll
                for (int tp = 0; tp < 2; tp++) {
                    uint32_t bbq[4];
                    LDMX4(bbq, sbase + b_offs + stg + tp*(16*80) + kh*32);
                    #pragma unroll
                    for (int q = 0; q < 2; q++) {
                        int nt = tp*2 + q;
                        if (nt < 3)
                            MMA16816(acc[nt], ah, bbq[2*q], bbq[2*q+1]);
                    }
                }
            }
            __syncthreads();
        }

        // epilogue -> smem offsets
        int mA = wid*16 + (lid >> 2);
        int mB = mA + 8;
        #pragma unroll
        for (int nt = 0; nt < 3; nt++) {
            int j0 = nt*8 + (lid & 3)*2;
            float* d = acc[nt];
            if (j0 < 18) {
                float bv = b_off[j0];
                s_off[j0*128 + mA] = d[0] + bv;
                s_off[j0*128 + mB] = d[2] + bv;
            }
            if (j0 + 1 < 18) {
                float bv = b_off[j0 + 1];
                s_off[(j0 + 1)*128 + mA] = d[1] + bv;
                s_off[(j0 + 1)*128 + mB] = d[3] + bv;
            }
        }
    }
    __syncthreads();

    // ================= phase 2: fused sample + main GEMM =================
    const int warpM = wid & 1, warpN = wid >> 1;   // 2 x 4, warp tile 64x64

    float acc[4][8][4];
    #pragma unroll
    for (int mt = 0; mt < 4; mt++)
        #pragma unroll
        for (int nt = 0; nt < 8; nt++)
            #pragma unroll
            for (int j = 0; j < 4; j++) acc[mt][nt][j] = 0.f;

    const uint32_t a_off = (uint32_t)((warpM*64 + (lid & 15)) * 80 + (lid >> 4) * 16);
    const uint32_t bm_off = (uint32_t)((warpN*64 + (lid & 7) + ((lid >> 4) & 1)*8) * 80
                                       + ((lid >> 3) & 1) * 16);

    __half2 gh[2][4];
    uint32_t gb[2][4];
    const int growl[2] = { wid*16 + (lid >> 2), wid*16 + 8 + (lid >> 2) };
    const uint32_t chb = (uint32_t)((lid & 3) * 16);

    auto calc_tap = [&](int tap) {
        #pragma unroll
        for (int it = 0; it < 2; it++) {
            int pr = growl[it];
            int p = pbase + pr;
            int y = (p >> 6) & 63, x = p & 63;
            float dy = s_off[(2*tap)*128 + pr];
            float dx = s_off[(2*tap + 1)*128 + pr];
            float py = (float)(y - 1 + tap/3) + dy;
            float px = (float)(x - 1 + tap%3) + dx;
            float y0f = floorf(py), x0f = floorf(px);
            float ly = py - y0f, lx = px - x0f;
            int yy0 = (int)y0f, x0i = (int)x0f;
            int yy1 = yy0 + 1,  x1 = x0i + 1;
            float vy0 = (yy0 >= 0 && yy0 < 64) ? 1.f : 0.f;
            float vy1 = (yy1 >= 0 && yy1 < 64) ? 1.f : 0.f;
            float vx0 = (x0i >= 0 && x0i < 64) ? 1.f : 0.f;
            float vx1 = (x1  >= 0 && x1  < 64) ? 1.f : 0.f;
            gh[it][0] = __float2half2_rn((1.f-ly)*(1.f-lx)*vy0*vx0);
            gh[it][1] = __float2half2_rn((1.f-ly)*lx      *vy0*vx1);
            gh[it][2] = __float2half2_rn(ly      *(1.f-lx)*vy1*vx0);
            gh[it][3] = __float2half2_rn(ly      *lx      *vy1*vx1);
            int y0c = min(max(yy0, 0), 63), y1c = min(max(yy1, 0), 63);
            int x0c = min(max(x0i, 0), 63), x1c = min(max(x1,  0), 63);
            uint32_t rowb = (uint32_t)(bb << 12);
            gb[it][0] = (rowb + (y0c << 6) + x0c) << 9;
            gb[it][1] = (rowb + (y0c << 6) + x1c) << 9;
            gb[it][2] = (rowb + (y1c << 6) + x0c) << 9;
            gb[it][3] = (rowb + (y1c << 6) + x1c) << 9;
        }
    };

    const char* nb = (const char*)g_nhwcH;

    auto gather = [&](int it, int c0, uint4* cd) {
        uint32_t cho = (uint32_t)(c0 * 2) + chb;
        cd[0] = *(const uint4*)(nb + gb[it][0] + cho);
        cd[1] = *(const uint4*)(nb + gb[it][1] + cho);
        cd[2] = *(const uint4*)(nb + gb[it][2] + cho);
        cd[3] = *(const uint4*)(nb + gb[it][3] + cho);
    };

    auto combine_sts = [&](int it, const uint4* cd, uint32_t abuf_off) {
        uint4 pk;
        __half2* po = (__half2*)&pk;
        const __half2* f0 = (const __half2*)&cd[0];
        const __half2* f1 = (const __half2*)&cd[1];
        const __half2* f2 = (const __half2*)&cd[2];
        const __half2* f3 = (const __half2*)&cd[3];
        #pragma unroll
        for (int j = 0; j < 4; j++) {
            __half2 r = __hmul2(gh[it][0], f0[j]);
            r = __hfma2(gh[it][1], f1[j], r);
            r = __hfma2(gh[it][2], f2[j], r);
            r = __hfma2(gh[it][3], f3[j], r);
            po[j] = r;
        }
        *(uint4*)(dsmp + abuf_off + growl[it]*80 + (lid & 3)*16) = pk;
    };

    // prologue: A(0); B(0..2) already prefetched before phase 1
    calc_tap(0);
    {
        uint4 cd[4];
        gather(0, 0, cd); combine_sts(0, cd, 0);
        gather(1, 0, cd); combine_sts(1, cd, 0);
    }

    for (int c = 0; c < NCH; c++) {
        if (c + 3 < NCH) {
            asm volatile("cp.async.wait_group 2;" ::: "memory");
        } else if (c + 2 < NCH) {
            asm volatile("cp.async.wait_group 1;" ::: "memory");
        } else {
            asm volatile("cp.async.wait_group 0;" ::: "memory");
        }
        __syncthreads();

        // stage (c+3)&3 was fully consumed in chunk c-1; safe to refill now,
        // giving the cp.async a full chunk of MMA shadow
        if (c + 3 < NCH) loadB(c + 3, (c + 3) & 3);

        const int prep = (c + 1 < NCH);
        const int cn = c + 1;
        if (prep && ((cn & 7) == 0)) calc_tap(cn >> 3);
        const int c0n = (cn & 7) * 32;
        const uint32_t abuf_n = (uint32_t)((cn & 1) * APL);

        uint32_t sbB = sbase + BBASE + (c & 3) * BPL;
        uint32_t sbA = sbase + (c & 1) * APL;

        uint4 cd0[4], cd1[4];
        if (prep) gather(0, c0n, cd0);

        // kh = 0
        {
            uint32_t ah[4][4];
            #pragma unroll
            for (int mt = 0; mt < 4; mt++)
                LDMX4(ah[mt], sbA + a_off + mt*(16*80));
            #pragma unroll
            for (int tp = 0; tp < 4; tp++) {
                uint32_t bfr[4];
                LDMX4(bfr, sbB + bm_off + tp*(16*80));
                #pragma unroll
                for (int q = 0; q < 2; q++) {
                    int nt = tp*2 + q;
                    #pragma unroll
                    for (int mt = 0; mt < 4; mt++)
                        MMA16816(acc[mt][nt], ah[mt], bfr[2*q], bfr[2*q+1]);
                }
            }
        }
        if (prep) { combine_sts(0, cd0, abuf_n); gather(1, c0n, cd1); }
        // kh = 1
        {
            uint32_t ah[4][4];
            #pragma unroll
            for (int mt = 0; mt < 4; mt++)
                LDMX4(ah[mt], sbA + a_off + mt*(16*80) + 32);
            #pragma unroll
            for (int tp = 0; tp < 4; tp++) {
                uint32_t bfr[4];
                LDMX4(bfr, sbB + bm_off + tp*(16*80) + 32);
                #pragma unroll
                for (int q = 0; q < 2; q++) {
                    int nt = tp*2 + q;
                    #pragma unroll
                    for (int mt = 0; mt < 4; mt++)
                        MMA16816(acc[mt][nt], ah[mt], bfr[2*q], bfr[2*q+1]);
                }
            }
        }
        if (prep) combine_sts(1, cd1, abuf_n);
    }

    // epilogue: bias + relu, NCHW stores
    #pragma unroll
    for (int mt = 0; mt < 4; mt++) {
        int mA = m0 + warpM*64 + mt*16 + (lid >> 2);
        int mB = mA + 8;
        int bA = mA >> 12, bB = mB >> 12;
        int pA = mA & 4095, pB = mB & 4095;
        #pragma unroll
        for (int nt = 0; nt < 8; nt++) {
            int o = warpN*64 + nt*8 + (lid & 3)*2;
            float bv0 = g_bias2[o], bv1 = g_bias2[o + 1];
            float* d = acc[mt][nt];
            out[((size_t)bA << 20) + ((size_t)o << 12)     + pA] = fmaxf(d[0] + bv0, 0.f);
            out[((size_t)bA << 20) + ((size_t)(o+1) << 12) + pA] = fmaxf(d[1] + bv1, 0.f);
            out[((size_t)bB << 20) + ((size_t)o << 12)     + pB] = fmaxf(d[2] + bv0, 0.f);
            out[((size_t)bB << 20) + ((size_t)(o+1) << 12) + pB] = fmaxf(d[3] + bv1, 0.f);
        }
    }
}

// ---------------- launch ----------------
extern "C" void kernel_launch(void* const* d_in, const int* in_sizes, int n_in,
                              void* d_out, int out_size) {
    const float* input  = (const float*)d_in[0];
    const float* w_off  = (const float*)d_in[1];
    const float* b_off  = (const float*)d_in[2];
    const float* weight = (const float*)d_in[3];
    const float* bias   = (const float*)d_in[4];
    const float* gamma  = (const float*)d_in[5];
    const float* beta   = (const float*)d_in[6];
    const float* mean   = (const float*)d_in[7];
    const float* var    = (const float*)d_in[8];
    float* out = (float*)d_out;

    cudaFuncSetAttribute(k_fused_all, cudaFuncAttributeMaxDynamicSharedMemorySize, SMEMSZ);

    k_transpose_prep<<<dim3(2, 6, 256), dim3(32, 8)>>>(input, weight, w_off, bias, gamma, beta, mean, var);
    k_fused_all<<<Md/128, 256, SMEMSZ>>>(out, b_off);
}